// round 5
// baseline (speedup 1.0000x reference)
#include <cuda_runtime.h>
#include <cuda_bf16.h>
#include <cstdint>

#define NN 2048
#define BB 64
#define TT 512
#define CTAS 128
#define THREADS 512
#define PITCHB 4112                 // 2048*2 + 16 bytes, conflict-free ldmatrix rows

// ---- shared memory layout ----
#define OFF_WHI 0
#define OFF_WLO (16 * PITCHB)               // 65792
#define OFF_SPK (32 * PITCHB)               // 131584
#define SPK_STRIDE 68                       // u32 words per spike row (padded)
#define OFF_MEM (OFF_SPK + 64 * SPK_STRIDE * 4)   // 148992
#define OFF_RED (OFF_MEM + 64 * 16 * 4)           // 153088
#define SMEM_TOTAL (OFF_RED + 8 * 1024 * 4)       // 185856

// ---- persistent device state ----
__device__ __align__(16) __nv_bfloat16 g_Whi[NN * NN];    // [n][k] = 0.1*eff^T, hi
__device__ __align__(16) __nv_bfloat16 g_Wlo[NN * NN];    // residual
__device__ __align__(16) uint32_t g_spk0[BB * (NN / 32)]; // bit-permuted packed spikes
__device__ __align__(16) uint32_t g_spk1[BB * (NN / 32)];
__device__ uint32_t g_bar;

// Spike bit permutation: within each 16-bit half (h = k>=16), local c = k&15 sits at
//   np(c) = ((c&7)>>1)*4 + (c&1) + 2*((c>>3)&1)
// so nibble q of a half = bits {k=2q, 2q+1, 2q+8, 2q+9}: one lane's A-pair bits.

// ---- helpers ----
__device__ __forceinline__ uint32_t smem_u32(const void* p) {
    uint32_t a;
    asm("{ .reg .u64 t; cvta.to.shared.u64 t, %1; cvt.u32.u64 %0, t; }" : "=r"(a) : "l"(p));
    return a;
}

__device__ __forceinline__ void ldsm2(uint32_t* r, uint32_t addr) {
    asm volatile("ldmatrix.sync.aligned.m8n8.x2.shared.b16 {%0,%1}, [%2];"
                 : "=r"(r[0]), "=r"(r[1]) : "r"(addr));
}

__device__ __forceinline__ void mma_bf16(float* c, const uint32_t* a, uint32_t b0, uint32_t b1) {
    asm volatile(
        "mma.sync.aligned.m16n8k16.row.col.f32.bf16.bf16.f32 "
        "{%0,%1,%2,%3},{%4,%5,%6,%7},{%8,%9},{%0,%1,%2,%3};"
        : "+f"(c[0]), "+f"(c[1]), "+f"(c[2]), "+f"(c[3])
        : "r"(a[0]), "r"(a[1]), "r"(a[2]), "r"(a[3]), "r"(b0), "r"(b1));
}

// nibble bits {b0,b1} -> bf16x2 {1|0, 1|0} via integer multiply (fma pipe)
__device__ __forceinline__ uint32_t nib2bf(uint32_t t) {
    return (t & 1u) * 0x3F80u + (t & 2u) * 0x1FC00000u;
}

// ---- prep: transpose + zero diag + 0.1 scale + bf16 hi/lo split, plus state init ----
__global__ void prep_kernel(const float* __restrict__ rec) {
    __shared__ float tile[32][33];
    int k = blockIdx.y * 32 + threadIdx.y;
    int n = blockIdx.x * 32 + threadIdx.x;
    tile[threadIdx.y][threadIdx.x] = rec[k * NN + n];

    int fb = blockIdx.y * gridDim.x + blockIdx.x;
    int ft = threadIdx.y * 32 + threadIdx.x;
    if (fb < 4)      g_spk0[fb * 1024 + ft] = 0u;
    else if (fb < 8) g_spk1[(fb - 4) * 1024 + ft] = 0u;
    else if (fb == 8 && ft == 0) g_bar = 0u;

    __syncthreads();
    int nn = blockIdx.x * 32 + threadIdx.y;
    int kk = blockIdx.y * 32 + threadIdx.x;
    float w = tile[threadIdx.x][threadIdx.y];      // rec[kk][nn]
    float v = (nn == kk) ? 0.0f : 0.1f * w;
    __nv_bfloat16 hi = __float2bfloat16(v);
    float resid = v - __bfloat162float(hi);
    g_Whi[nn * NN + kk] = hi;
    g_Wlo[nn * NN + kk] = __float2bfloat16(resid);
}

// ---- persistent RSNN kernel: 128 CTAs, one per 16-neuron slice, 16 warps ----
__global__ void __launch_bounds__(THREADS, 1)
rsnn_kernel(const float* __restrict__ x, float* __restrict__ out) {
    extern __shared__ char smem[];
    const uint32_t sbase = smem_u32(smem);

    const int tid = threadIdx.x;
    const int wid = tid >> 5;
    const int lane = tid & 31;
    const int n0 = blockIdx.x * 16;

    const int kh = wid >> 1;            // k-eighth (8 u32 words)
    const int nh = wid & 1;             // n-half (8 columns)

    // ---- load weight slice into SMEM once (hi + lo, pitched) ----
    for (int i = tid; i < 16 * 256; i += THREADS) {
        int row = i >> 8, c = i & 255;
        *(uint4*)(smem + OFF_WHI + row * PITCHB + c * 16) =
            *(const uint4*)(g_Whi + (size_t)(n0 + row) * NN + c * 8);
        *(uint4*)(smem + OFF_WLO + row * PITCHB + c * 16) =
            *(const uint4*)(g_Wlo + (size_t)(n0 + row) * NN + c * 8);
    }
    for (int i = tid; i < 64 * 16; i += THREADS)
        ((float*)(smem + OFF_MEM))[i] = 0.0f;
    __syncthreads();

    // per-thread constants
    const int rowq = lane >> 2;           // 0..7
    const int q4 = (lane & 3) * 4;        // nibble shift within a 16-bit half
    const int c0 = (lane & 3) * 2;
    uint32_t ldsm_off;
    {
        int grp = (lane >> 3) & 1;                    // which k-octet of the k16
        int row = nh * 8 + (lane & 7);                // local neuron row
        ldsm_off = row * PITCHB + grp * 16;
    }
    const int eb = tid >> 2;              // epilogue batch row 0..63 (tid<256)
    const int eq = (tid & 3) * 4;         // epilogue col base 0..12
    const int wsel = n0 >> 5;
    const int hsh = ((n0 >> 4) & 1) * 16;

    int npos[4];
    uint32_t pmask[4];
    #pragma unroll
    for (int i = 0; i < 4; ++i) {
        int c = eq + i;
        npos[i] = ((c & 7) >> 1) * 4 + (c & 1) + 2 * ((c >> 3) & 1);
        pmask[i] = 1u << (hsh + npos[i]);
    }

    uint32_t* const spkS = (uint32_t*)(smem + OFF_SPK);
    float* const memS = (float*)(smem + OFF_MEM);
    float* const redS = (float*)(smem + OFF_RED);

    for (int t = 0; t < TT; ++t) {
        const uint32_t* gsrc = (t & 1) ? g_spk1 : g_spk0;
        uint32_t* gdst = (t & 1) ? g_spk0 : g_spk1;

        // ---- prefetch x for this step (epilogue threads only) ----
        float4 xv = make_float4(0.f, 0.f, 0.f, 0.f);
        if (tid < 256)
            xv = __ldg((const float4*)(x + ((size_t)eb * TT + t) * NN + n0 + eq));

        // ---- stage packed spikes [64 x 64 u32] -> padded SMEM rows ----
        {
            const uint4* src = (const uint4*)gsrc;
            #pragma unroll
            for (int i = tid; i < 1024; i += THREADS) {
                int row = i >> 4, c4 = i & 15;
                uint4 v = __ldcg(src + i);
                *(uint4*)(smem + OFF_SPK + (row * SPK_STRIDE + c4 * 4) * 4) = v;
            }
        }
        __syncthreads();

        // ---- GEMM: warp = (k-eighth, n-half), all 4 m-tiles ----
        float acc[4][4];
        #pragma unroll
        for (int m = 0; m < 4; ++m)
            #pragma unroll
            for (int e = 0; e < 4; ++e) acc[m][e] = 0.0f;

        #pragma unroll 2
        for (int j = 0; j < 8; ++j) {
            const int widx = (kh << 3) + j;           // u32 spike word index
            uint32_t bh[2][2], bl[2][2];
            #pragma unroll
            for (int h = 0; h < 2; ++h) {
                const int kt = widx * 2 + h;
                ldsm2(bh[h], sbase + OFF_WHI + ldsm_off + kt * 32);
                ldsm2(bl[h], sbase + OFF_WLO + ldsm_off + kt * 32);
            }
            #pragma unroll
            for (int m = 0; m < 4; ++m) {
                const uint32_t w0 = spkS[(m * 16 + rowq) * SPK_STRIDE + widx];
                const uint32_t w1 = spkS[(m * 16 + rowq + 8) * SPK_STRIDE + widx];
                #pragma unroll
                for (int h = 0; h < 2; ++h) {
                    const uint32_t t0 = w0 >> (h * 16 + q4);
                    const uint32_t t1 = w1 >> (h * 16 + q4);
                    uint32_t a[4];
                    a[0] = nib2bf(t0);
                    a[1] = nib2bf(t1);
                    a[2] = nib2bf(t0 >> 2);
                    a[3] = nib2bf(t1 >> 2);
                    mma_bf16(acc[m], a, bh[h][0], bh[h][1]);
                    mma_bf16(acc[m], a, bl[h][0], bl[h][1]);
                }
            }
        }

        // ---- dump partials: warps sharing kh fill disjoint column halves ----
        {
            float* pw = redS + kh * 1024;
            const int col = nh * 8 + c0;
            #pragma unroll
            for (int m = 0; m < 4; ++m) {
                const int r = m * 16 + rowq;
                *(float2*)(pw + r * 16 + col) = make_float2(acc[m][0], acc[m][1]);
                *(float2*)(pw + (r + 8) * 16 + col) = make_float2(acc[m][2], acc[m][3]);
            }
        }
        __syncthreads();

        // ---- reduce 8 partials + LIF epilogue (threads 0..255) ----
        unsigned s0 = 0, s1 = 0, s2 = 0, s3 = 0;
        if (tid < 256) {
            float4 s = *(float4*)(redS + eb * 16 + eq);
            #pragma unroll
            for (int w = 1; w < 8; ++w) {
                float4 p = *(float4*)(redS + w * 1024 + eb * 16 + eq);
                s.x += p.x; s.y += p.y; s.z += p.z; s.w += p.w;
            }

            float4 mv = *(float4*)(memS + eb * 16 + eq);
            const uint32_t pw = spkS[eb * SPK_STRIDE + wsel];

            float cur0 = xv.x + s.x, cur1 = xv.y + s.y;
            float cur2 = xv.z + s.z, cur3 = xv.w + s.w;
            float m0 = (pw & pmask[0]) ? cur0 : fmaf(0.96f, mv.x, cur0);
            float m1 = (pw & pmask[1]) ? cur1 : fmaf(0.96f, mv.y, cur1);
            float m2 = (pw & pmask[2]) ? cur2 : fmaf(0.96f, mv.z, cur2);
            float m3 = (pw & pmask[3]) ? cur3 : fmaf(0.96f, mv.w, cur3);

            s0 = (m0 >= 0.5f); s1 = (m1 >= 0.5f);
            s2 = (m2 >= 0.5f); s3 = (m3 >= 0.5f);

            *(float4*)(memS + eb * 16 + eq) = make_float4(m0, m1, m2, m3);

            unsigned v = (s0 << npos[0]) | (s1 << npos[1]) | (s2 << npos[2]) | (s3 << npos[3]);
            v |= __shfl_xor_sync(0xFFFFFFFFu, v, 1);
            v |= __shfl_xor_sync(0xFFFFFFFFu, v, 2);
            if ((tid & 3) == 0)
                ((uint16_t*)gdst)[eb * 128 + blockIdx.x] = (uint16_t)v;
        }

        // ---- barrier arrive (spikes visible), overlap out-store with wait ----
        __syncthreads();
        if (tid == 0)
            asm volatile("red.release.gpu.global.add.u32 [%0], 1;" :: "l"(&g_bar) : "memory");

        if (tid < 256)
            *(float4*)(out + ((size_t)eb * TT + t) * NN + n0 + eq) =
                make_float4((float)s0, (float)s1, (float)s2, (float)s3);

        if (tid == 0) {
            const unsigned tgt = (unsigned)(CTAS * (t + 1));
            unsigned bv;
            do {
                asm volatile("ld.acquire.gpu.global.u32 %0, [%1];" : "=r"(bv) : "l"(&g_bar) : "memory");
            } while (bv < tgt);
        }
        __syncthreads();
    }
}

// ---- launch ----
extern "C" void kernel_launch(void* const* d_in, const int* in_sizes, int n_in,
                              void* d_out, int out_size) {
    const float* x = (const float*)d_in[0];
    const float* rec = (const float*)d_in[1];
    if (n_in >= 2 && in_sizes[0] == NN * NN) {
        x = (const float*)d_in[1];
        rec = (const float*)d_in[0];
    }
    float* out = (float*)d_out;

    cudaFuncSetAttribute(rsnn_kernel, cudaFuncAttributeMaxDynamicSharedMemorySize, SMEM_TOTAL);

    dim3 cg(NN / 32, NN / 32), cb(32, 32);
    prep_kernel<<<cg, cb>>>(rec);
    rsnn_kernel<<<CTAS, THREADS, SMEM_TOTAL>>>(x, out);
}

// round 6
// speedup vs baseline: 1.5205x; 1.5205x over previous
#include <cuda_runtime.h>
#include <cuda_bf16.h>
#include <cstdint>

#define NN 2048
#define BB 64
#define TT 512
#define CTAS 128
#define THREADS 512
#define PITCHB 4112                 // 2048*2 + 16 bytes, conflict-free ldmatrix rows

// ---- shared memory layout ----
#define OFF_WHI 0
#define OFF_WLO (16 * PITCHB)               // 65792
#define OFF_SPK (32 * PITCHB)               // 131584
#define SPK_STRIDE 68                       // u32 words per spike row (padded)
#define OFF_MEM (OFF_SPK + 64 * SPK_STRIDE * 4)   // 148992
#define OFF_RED (OFF_MEM + 64 * 16 * 4)           // 153088
#define OFF_LUT (OFF_RED + 16 * 1024 * 4)         // 218624
#define SMEM_TOTAL (OFF_LUT + 256)                // 218880

// ---- persistent device state ----
__device__ __align__(16) __nv_bfloat16 g_Whi[NN * NN];    // [n][k] = 0.1*eff^T, hi
__device__ __align__(16) __nv_bfloat16 g_Wlo[NN * NN];    // residual
__device__ __align__(16) uint32_t g_spk0[BB * (NN / 32)]; // bit-permuted packed spikes
__device__ __align__(16) uint32_t g_spk1[BB * (NN / 32)];
__device__ uint32_t g_bar;

// Spike bit permutation: within each 16-bit half (h = k>=16), local c = k&15 sits at
//   np(c) = ((c&7)>>1)*4 + (c&1) + 2*((c>>3)&1)
// so nibble q of a half = bits {k=2q, 2q+1, 2q+8, 2q+9}: one lane's A-pair bits.

// ---- helpers ----
__device__ __forceinline__ uint32_t smem_u32(const void* p) {
    uint32_t a;
    asm("{ .reg .u64 t; cvta.to.shared.u64 t, %1; cvt.u32.u64 %0, t; }" : "=r"(a) : "l"(p));
    return a;
}

__device__ __forceinline__ void ldsm4(uint32_t* r, uint32_t addr) {
    asm volatile("ldmatrix.sync.aligned.m8n8.x4.shared.b16 {%0,%1,%2,%3}, [%4];"
                 : "=r"(r[0]), "=r"(r[1]), "=r"(r[2]), "=r"(r[3]) : "r"(addr));
}

__device__ __forceinline__ void mma_bf16(float* c, const uint32_t* a, uint32_t b0, uint32_t b1) {
    asm volatile(
        "mma.sync.aligned.m16n8k16.row.col.f32.bf16.bf16.f32 "
        "{%0,%1,%2,%3},{%4,%5,%6,%7},{%8,%9},{%0,%1,%2,%3};"
        : "+f"(c[0]), "+f"(c[1]), "+f"(c[2]), "+f"(c[3])
        : "r"(a[0]), "r"(a[1]), "r"(a[2]), "r"(a[3]), "r"(b0), "r"(b1));
}

// ---- prep: transpose + zero diag + 0.1 scale + bf16 hi/lo split, plus state init ----
__global__ void prep_kernel(const float* __restrict__ rec) {
    __shared__ float tile[32][33];
    int k = blockIdx.y * 32 + threadIdx.y;
    int n = blockIdx.x * 32 + threadIdx.x;
    tile[threadIdx.y][threadIdx.x] = rec[k * NN + n];

    int fb = blockIdx.y * gridDim.x + blockIdx.x;
    int ft = threadIdx.y * 32 + threadIdx.x;
    if (fb < 4)      g_spk0[fb * 1024 + ft] = 0u;
    else if (fb < 8) g_spk1[(fb - 4) * 1024 + ft] = 0u;
    else if (fb == 8 && ft == 0) g_bar = 0u;

    __syncthreads();
    int nn = blockIdx.x * 32 + threadIdx.y;
    int kk = blockIdx.y * 32 + threadIdx.x;
    float w = tile[threadIdx.x][threadIdx.y];      // rec[kk][nn]
    float v = (nn == kk) ? 0.0f : 0.1f * w;
    __nv_bfloat16 hi = __float2bfloat16(v);
    float resid = v - __bfloat162float(hi);
    g_Whi[nn * NN + kk] = hi;
    g_Wlo[nn * NN + kk] = __float2bfloat16(resid);
}

// ---- persistent RSNN kernel: 128 CTAs, one per 16-neuron slice, 16 warps ----
__global__ void __launch_bounds__(THREADS, 1)
rsnn_kernel(const float* __restrict__ x, float* __restrict__ out) {
    extern __shared__ char smem[];
    const uint32_t sbase = smem_u32(smem);

    const int tid = threadIdx.x;
    const int wid = tid >> 5;           // warp = k-sixteenth (4 u32 spike words)
    const int lane = tid & 31;
    const int n0 = blockIdx.x * 16;

    // ---- load weight slice into SMEM once (hi + lo, pitched) ----
    for (int i = tid; i < 16 * 256; i += THREADS) {
        int row = i >> 8, c = i & 255;
        *(uint4*)(smem + OFF_WHI + row * PITCHB + c * 16) =
            *(const uint4*)(g_Whi + (size_t)(n0 + row) * NN + c * 8);
        *(uint4*)(smem + OFF_WLO + row * PITCHB + c * 16) =
            *(const uint4*)(g_Wlo + (size_t)(n0 + row) * NN + c * 8);
    }
    for (int i = tid; i < 64 * 16; i += THREADS)
        ((float*)(smem + OFF_MEM))[i] = 0.0f;
    // nibble -> (a_low, a_high) bf16x2 LUT; 16 x 8B = one bank sweep, conflict-free
    if (tid < 16) {
        uint2 e;
        e.x = ((tid & 1) ? 0x00003F80u : 0u) | ((tid & 2) ? 0x3F800000u : 0u);
        e.y = ((tid & 4) ? 0x00003F80u : 0u) | ((tid & 8) ? 0x3F800000u : 0u);
        ((uint2*)(smem + OFF_LUT))[tid] = e;
    }
    __syncthreads();

    // per-thread constants
    const int rowq = lane >> 2;           // 0..7
    const int q4 = (lane & 3) * 4;        // nibble shift within a 16-bit half
    const int c0 = (lane & 3) * 2;
    uint32_t ldsm_off;
    {
        int grp = lane >> 3;                          // 8x8 matrix select
        int row = ((grp >> 1) << 3) + (lane & 7);     // local neuron row 0..15
        int koff = (grp & 1) * 8;
        ldsm_off = row * PITCHB + koff * 2;
    }
    const int eb = tid >> 2;              // epilogue batch row 0..63 (tid<256)
    const int eq = (tid & 3) * 4;         // epilogue col base 0..12
    const int wsel = n0 >> 5;
    const int hsh = ((n0 >> 4) & 1) * 16;

    int npos[4];
    uint32_t pmask[4];
    #pragma unroll
    for (int i = 0; i < 4; ++i) {
        int c = eq + i;
        npos[i] = ((c & 7) >> 1) * 4 + (c & 1) + 2 * ((c >> 3) & 1);
        pmask[i] = 1u << (hsh + npos[i]);
    }

    uint32_t* const spkS = (uint32_t*)(smem + OFF_SPK);
    float* const memS = (float*)(smem + OFF_MEM);
    float* const redS = (float*)(smem + OFF_RED);
    const uint2* const lutS = (const uint2*)(smem + OFF_LUT);

    for (int t = 0; t < TT; ++t) {
        const uint32_t* gsrc = (t & 1) ? g_spk1 : g_spk0;
        uint32_t* gdst = (t & 1) ? g_spk0 : g_spk1;

        // ---- prefetch x for this step (epilogue threads only) ----
        float4 xv = make_float4(0.f, 0.f, 0.f, 0.f);
        if (tid < 256)
            xv = __ldg((const float4*)(x + ((size_t)eb * TT + t) * NN + n0 + eq));

        // ---- stage packed spikes [64 x 64 u32] -> padded SMEM rows ----
        {
            const uint4* src = (const uint4*)gsrc;
            #pragma unroll
            for (int i = tid; i < 1024; i += THREADS) {
                int row = i >> 4, c4 = i & 15;
                uint4 v = __ldcg(src + i);
                *(uint4*)(smem + OFF_SPK + (row * SPK_STRIDE + c4 * 4) * 4) = v;
            }
        }
        __syncthreads();

        // ---- GEMM: warp owns a k-sixteenth, all 4 m-tiles, full 16 columns ----
        float acc[4][2][4];
        #pragma unroll
        for (int m = 0; m < 4; ++m)
            #pragma unroll
            for (int nh = 0; nh < 2; ++nh)
                #pragma unroll
                for (int e = 0; e < 4; ++e) acc[m][nh][e] = 0.0f;

        #pragma unroll 2
        for (int j = 0; j < 4; ++j) {
            const int widx = (wid << 2) + j;          // u32 spike word index
            uint32_t bh[2][4], bl[2][4];
            #pragma unroll
            for (int h = 0; h < 2; ++h) {
                const int kt = widx * 2 + h;
                ldsm4(bh[h], sbase + OFF_WHI + ldsm_off + kt * 32);
                ldsm4(bl[h], sbase + OFF_WLO + ldsm_off + kt * 32);
            }
            #pragma unroll
            for (int m = 0; m < 4; ++m) {
                const uint32_t w0 = spkS[(m * 16 + rowq) * SPK_STRIDE + widx];
                const uint32_t w1 = spkS[(m * 16 + rowq + 8) * SPK_STRIDE + widx];
                #pragma unroll
                for (int h = 0; h < 2; ++h) {
                    uint2 u0 = lutS[(w0 >> (h * 16 + q4)) & 0xFu];
                    uint2 u1 = lutS[(w1 >> (h * 16 + q4)) & 0xFu];
                    uint32_t a[4] = {u0.x, u1.x, u0.y, u1.y};
                    mma_bf16(acc[m][0], a, bh[h][0], bh[h][1]);
                    mma_bf16(acc[m][1], a, bh[h][2], bh[h][3]);
                    mma_bf16(acc[m][0], a, bl[h][0], bl[h][1]);
                    mma_bf16(acc[m][1], a, bl[h][2], bl[h][3]);
                }
            }
        }

        // ---- dump per-warp partials (16 regions of 64x16) ----
        {
            float* pw = redS + wid * 1024;
            #pragma unroll
            for (int m = 0; m < 4; ++m)
                #pragma unroll
                for (int nh = 0; nh < 2; ++nh) {
                    const int col = nh * 8 + c0;
                    const int r = m * 16 + rowq;
                    *(float2*)(pw + r * 16 + col) = make_float2(acc[m][nh][0], acc[m][nh][1]);
                    *(float2*)(pw + (r + 8) * 16 + col) = make_float2(acc[m][nh][2], acc[m][nh][3]);
                }
        }
        __syncthreads();

        // ---- reduce 16 partials + LIF epilogue (threads 0..255) ----
        unsigned s0 = 0, s1 = 0, s2 = 0, s3 = 0;
        if (tid < 256) {
            float4 s = *(float4*)(redS + eb * 16 + eq);
            #pragma unroll
            for (int w = 1; w < 16; ++w) {
                float4 p = *(float4*)(redS + w * 1024 + eb * 16 + eq);
                s.x += p.x; s.y += p.y; s.z += p.z; s.w += p.w;
            }

            float4 mv = *(float4*)(memS + eb * 16 + eq);
            const uint32_t pw = spkS[eb * SPK_STRIDE + wsel];

            float cur0 = xv.x + s.x, cur1 = xv.y + s.y;
            float cur2 = xv.z + s.z, cur3 = xv.w + s.w;
            float m0 = (pw & pmask[0]) ? cur0 : fmaf(0.96f, mv.x, cur0);
            float m1 = (pw & pmask[1]) ? cur1 : fmaf(0.96f, mv.y, cur1);
            float m2 = (pw & pmask[2]) ? cur2 : fmaf(0.96f, mv.z, cur2);
            float m3 = (pw & pmask[3]) ? cur3 : fmaf(0.96f, mv.w, cur3);

            s0 = (m0 >= 0.5f); s1 = (m1 >= 0.5f);
            s2 = (m2 >= 0.5f); s3 = (m3 >= 0.5f);

            *(float4*)(memS + eb * 16 + eq) = make_float4(m0, m1, m2, m3);

            unsigned v = (s0 << npos[0]) | (s1 << npos[1]) | (s2 << npos[2]) | (s3 << npos[3]);
            v |= __shfl_xor_sync(0xFFFFFFFFu, v, 1);
            v |= __shfl_xor_sync(0xFFFFFFFFu, v, 2);
            if ((tid & 3) == 0)
                ((uint16_t*)gdst)[eb * 128 + blockIdx.x] = (uint16_t)v;
        }

        // ---- barrier arrive (spikes visible), overlap out-store with wait ----
        __syncthreads();
        if (tid == 0)
            asm volatile("red.release.gpu.global.add.u32 [%0], 1;" :: "l"(&g_bar) : "memory");

        if (tid < 256)
            *(float4*)(out + ((size_t)eb * TT + t) * NN + n0 + eq) =
                make_float4((float)s0, (float)s1, (float)s2, (float)s3);

        if (tid == 0) {
            const unsigned tgt = (unsigned)(CTAS * (t + 1));
            unsigned bv;
            do {
                asm volatile("ld.acquire.gpu.global.u32 %0, [%1];" : "=r"(bv) : "l"(&g_bar) : "memory");
            } while (bv < tgt);
        }
        __syncthreads();
    }
}

// ---- launch ----
extern "C" void kernel_launch(void* const* d_in, const int* in_sizes, int n_in,
                              void* d_out, int out_size) {
    const float* x = (const float*)d_in[0];
    const float* rec = (const float*)d_in[1];
    if (n_in >= 2 && in_sizes[0] == NN * NN) {
        x = (const float*)d_in[1];
        rec = (const float*)d_in[0];
    }
    float* out = (float*)d_out;

    cudaFuncSetAttribute(rsnn_kernel, cudaFuncAttributeMaxDynamicSharedMemorySize, SMEM_TOTAL);

    dim3 cg(NN / 32, NN / 32), cb(32, 32);
    prep_kernel<<<cg, cb>>>(rec);
    rsnn_kernel<<<CTAS, THREADS, SMEM_TOTAL>>>(x, out);
}